// round 14
// baseline (speedup 1.0000x reference)
#include <cuda_runtime.h>
#include <float.h>

// And_Convolution: out[n][s] = min_{k<16} ( in[n][4*s + k] * w[k] )
// N=1024, L=8192, KERNEL=16, STRIDE=4 -> OUTW = (L-16)/4 + 1 = 2045
//
// Decomposition: window s covers float4 indices u = s+d (d=0..3):
//   g_d(u) = min_c in4[u].c * w[4d+c];  out[s] = min_d g_d(s+d)
// Group i (32 outputs) needs only g_*(v[i]) and g_*(v[i+1]).
//
// Round-14: rolling-window pipeline, MLP_p1=3. All prior kernels
// front-batched 8-11 LDG.128 per warp; per the B300 cross-CTA L1tex
// spread model (spr = 1.10 + 25*(oe*MLP_p1-16)/T_CTA) that costs a
// 1.5-2.0x chip-level spread. Here a #pragma unroll 1 loop carries a
// 3-vector window (a,b,c) + the shared vector's g1/g2/g3 partials;
// only 3 loads are front-batched, 2 more issue per iteration.

#define ROW_L4   2048
#define OUTW     2045
#define TPB      128
#define CTA_OUT  1024                    // 4 warps * 256 outputs
#define CTAS_PER_ROW 2

typedef unsigned long long u64;

__device__ __forceinline__ u64 pk2(float a, float b) {
    u64 r; asm("mov.b64 %0, {%1, %2};" : "=l"(r) : "f"(a), "f"(b)); return r;
}
__device__ __forceinline__ u64 mul2(u64 a, u64 b) {
    u64 r; asm("mul.rn.f32x2 %0, %1, %2;" : "=l"(r) : "l"(a), "l"(b)); return r;
}
__device__ __forceinline__ float2 upk2(u64 p) {
    float x, y; asm("mov.b64 {%0, %1}, %2;" : "=f"(x), "=f"(y) : "l"(p));
    return make_float2(x, y);
}
// min over 4 components of v*w (v,w packed as lo=xy, hi=zw)
__device__ __forceinline__ float min4w_p(u64 vlo, u64 vhi, u64 wlo, u64 whi) {
    float2 a = upk2(mul2(vlo, wlo));
    float2 b = upk2(mul2(vhi, whi));
    return fminf(fminf(a.x, b.x), fminf(a.y, b.y));
}

__global__ __launch_bounds__(TPB)
void and_conv_kernel(const float4* __restrict__ in,
                     const float*  __restrict__ w,
                     float*        __restrict__ out)
{
    const int row   = blockIdx.x >> 1;
    const int chunk = blockIdx.x & 1;
    const int warp  = threadIdx.x >> 5;
    const int lane  = threadIdx.x & 31;
    const int wbase = chunk * CTA_OUT + warp * 256;   // warp's first output/f4

    const float4* __restrict__ rowp = in + (size_t)row * ROW_L4;
    float* __restrict__ orow = out + (size_t)row * OUTW;

    // Weights, packed (uniform -> broadcast, reg-resident)
    const float4* __restrict__ w4 = reinterpret_cast<const float4*>(w);
    u64 wlo[4], whi[4];
#pragma unroll
    for (int d = 0; d < 4; ++d) {
        float4 wd = __ldg(&w4[d]);
        wlo[d] = pk2(wd.x, wd.y);
        whi[d] = pk2(wd.z, wd.w);
    }

    // Prologue: window v[0], v[1], v[2]  (MLP_p1 = 3)
    float4 a = __ldg(&rowp[wbase + lane]);
    float4 b = __ldg(&rowp[wbase + 32 + lane]);
    int ic = wbase + 64 + lane;
    float4 c = __ldg(&rowp[ic < ROW_L4 - 1 ? ic : ROW_L4 - 1]);

    // Carried partials of 'a'
    u64 alo = pk2(a.x, a.y), ahi = pk2(a.z, a.w);
    float g1a = min4w_p(alo, ahi, wlo[1], whi[1]);
    float g2a = min4w_p(alo, ahi, wlo[2], whi[2]);
    float g3a = min4w_p(alo, ahi, wlo[3], whi[3]);

    const unsigned F = 0xFFFFFFFFu;

#pragma unroll 1
    for (int t = 0; t < 4; ++t) {
        const int base = wbase + 64 * t;          // iter covers groups 2t,2t+1

        // Partials of current window (a's g1..g3 carried from last iter)
        const u64 blo = pk2(b.x, b.y), bhi = pk2(b.z, b.w);
        const u64 clo = pk2(c.x, c.y), chi = pk2(c.z, c.w);
        const u64 aalo = pk2(a.x, a.y), aahi = pk2(a.z, a.w);

        float g0a = min4w_p(aalo, aahi, wlo[0], whi[0]);
        float g0b = min4w_p(blo,  bhi,  wlo[0], whi[0]);
        float g1b = min4w_p(blo,  bhi,  wlo[1], whi[1]);
        float g2b = min4w_p(blo,  bhi,  wlo[2], whi[2]);
        float g3b = min4w_p(blo,  bhi,  wlo[3], whi[3]);
        float g1c = min4w_p(clo,  chi,  wlo[1], whi[1]);
        float g2c = min4w_p(clo,  chi,  wlo[2], whi[2]);
        float g3c = min4w_p(clo,  chi,  wlo[3], whi[3]);

        // Group 2t: pair (a, b). Wrapped readers (lane >= 32-d) pull from
        // src lanes 0..d-1, which pre-select the next vector's partial.
        {
            float t1 = (lane < 1) ? g1b : g1a;
            float t2 = (lane < 2) ? g2b : g2a;
            float t3 = (lane < 3) ? g3b : g3a;
            float n1 = __shfl_sync(F, t1, (lane + 1) & 31);
            float n2 = __shfl_sync(F, t2, (lane + 2) & 31);
            float n3 = __shfl_sync(F, t3, (lane + 3) & 31);
            float r  = fminf(fminf(g0a, n1), fminf(n2, n3));
            int s = base + lane;
            if (s < OUTW) orow[s] = r;
        }
        // Group 2t+1: pair (b, c)
        {
            float t1 = (lane < 1) ? g1c : g1b;
            float t2 = (lane < 2) ? g2c : g2b;
            float t3 = (lane < 3) ? g3c : g3b;
            float n1 = __shfl_sync(F, t1, (lane + 1) & 31);
            float n2 = __shfl_sync(F, t2, (lane + 2) & 31);
            float n3 = __shfl_sync(F, t3, (lane + 3) & 31);
            float r  = fminf(fminf(g0b, n1), fminf(n2, n3));
            int s = base + 32 + lane;
            if (s < OUTW) orow[s] = r;
        }

        // Rotate window: a <- c (with carried partials), load next b, c
        if (t < 3) {
            a = c; g1a = g1c; g2a = g2c; g3a = g3c;
            int ib = base + 96 + lane;                 // v[2t+3], in-bounds
            b = __ldg(&rowp[ib]);
            int icn = base + 128 + lane;               // v[2t+4], clamp (halo)
            c = __ldg(&rowp[icn < ROW_L4 - 1 ? icn : ROW_L4 - 1]);
        }
    }
}

extern "C" void kernel_launch(void* const* d_in, const int* in_sizes, int n_in,
                              void* d_out, int out_size)
{
    const float* inp = (const float*)d_in[0];   // (N, 8192) fp32
    const float* w   = (const float*)d_in[1];   // (1, 16)   fp32

    const int N = in_sizes[0] / 8192;           // 1024

    and_conv_kernel<<<N * CTAS_PER_ROW, TPB>>>(
        reinterpret_cast<const float4*>(inp), w, (float*)d_out);
}

// round 15
// speedup vs baseline: 1.2407x; 1.2407x over previous
#include <cuda_runtime.h>
#include <float.h>

// And_Convolution: out[n][s] = min_{k<16} ( in[n][4*s + k] * w[k] )
// N=1024, L=8192, KERNEL=16, STRIDE=4 -> OUTW = (L-16)/4 + 1 = 2045
//
// Decomposition: window s covers float4 indices u = s+d (d=0..3):
//   g_d(u) = min_c in4[u].c * w[4d+c];  out[s] = min_d g_d(s+d)
//
// Round-15: R13's warp kernel (GROUPS=8, packed mul.rn.f32x2, predicated
// halo load, source-side-select single-shuffle assembly) relaunched as
// ONE balanced wave: 1024 CTAs (< n_conc ~1184), each CTA serially does
// both halves of its row. Removes the 1.73-wave split (73%-full second
// wave + wave transition) of the grid-2048 launch. Stores use __stcs so
// output lines don't evict the replay-hot input from L2.

#define ROW_L4   2048
#define OUTW     2045
#define TPB      128
#define GROUPS   8
#define WARP_OUT (32 * GROUPS)            // 256 outputs per warp-chunk

typedef unsigned long long u64;

__device__ __forceinline__ u64 pk2(float a, float b) {
    u64 r; asm("mov.b64 %0, {%1, %2};" : "=l"(r) : "f"(a), "f"(b)); return r;
}
__device__ __forceinline__ u64 mul2(u64 a, u64 b) {
    u64 r; asm("mul.rn.f32x2 %0, %1, %2;" : "=l"(r) : "l"(a), "l"(b)); return r;
}
__device__ __forceinline__ float2 upk2(u64 p) {
    float x, y; asm("mov.b64 {%0, %1}, %2;" : "=f"(x), "=f"(y) : "l"(p));
    return make_float2(x, y);
}
// min over 4 components of v*w, v/w pre-packed as (lo=xy, hi=zw)
__device__ __forceinline__ float min4w_p(u64 vlo, u64 vhi, u64 wlo, u64 whi) {
    float2 a = upk2(mul2(vlo, wlo));
    float2 b = upk2(mul2(vhi, whi));
    return fminf(fminf(a.x, b.x), fminf(a.y, b.y));
}

__global__ __launch_bounds__(TPB)
void and_conv_kernel(const float4* __restrict__ in,
                     const float*  __restrict__ w,
                     float*        __restrict__ out)
{
    const int row  = blockIdx.x;
    const int warp = threadIdx.x >> 5;
    const int lane = threadIdx.x & 31;

    const float4* __restrict__ rowp = in + (size_t)row * ROW_L4;
    float* __restrict__ orow = out + (size_t)row * OUTW;

    // Weights, packed into f32x2 pairs (uniform -> broadcast, reg-resident)
    const float4* __restrict__ w4 = reinterpret_cast<const float4*>(w);
    u64 wlo[4], whi[4];
#pragma unroll
    for (int d = 0; d < 4; ++d) {
        float4 wd = __ldg(&w4[d]);
        wlo[d] = pk2(wd.x, wd.y);
        whi[d] = pk2(wd.z, wd.w);
    }

    const unsigned F = 0xFFFFFFFFu;

#pragma unroll 1
    for (int half = 0; half < 2; ++half) {
        const int wbase = half * 1024 + warp * WARP_OUT; // first output/float4

        // ---- Phase 1: loads back-to-back (MLP=8 full + 1 partial) ----
        float4 v[GROUPS + 1];
#pragma unroll
        for (int i = 0; i < GROUPS; ++i)
            v[i] = __ldg(&rowp[wbase + 32 * i + lane]);   // always in-bounds
        v[GROUPS] = make_float4(0.f, 0.f, 0.f, 0.f);
        if (lane < 3) {                                   // only lanes 0-2 used
            int idx = wbase + 32 * GROUPS + lane;         // clamp at row end
            v[GROUPS] = __ldg(&rowp[idx < ROW_L4 - 1 ? idx : ROW_L4 - 1]);
        }

        // ---- Phase 2: partial mins (packed multiplies) ----
        float g0[GROUPS], g1[GROUPS + 1], g2[GROUPS + 1], g3[GROUPS + 1];
#pragma unroll
        for (int i = 0; i <= GROUPS; ++i) {
            const u64 vlo = pk2(v[i].x, v[i].y);
            const u64 vhi = pk2(v[i].z, v[i].w);
            if (i < GROUPS) g0[i] = min4w_p(vlo, vhi, wlo[0], whi[0]);
            g1[i] = min4w_p(vlo, vhi, wlo[1], whi[1]);
            g2[i] = min4w_p(vlo, vhi, wlo[2], whi[2]);
            g3[i] = min4w_p(vlo, vhi, wlo[3], whi[3]);
        }

        // ---- Phase 3: assemble via 3 shuffles per group, streaming store ----
#pragma unroll
        for (int i = 0; i < GROUPS; ++i) {
            // Wrapped readers (dest lane >= 32-d) hit src lanes 0..d-1,
            // which pre-select group i+1's partial. Only lanes 0-2 ever
            // export halo-derived values, so lane>=3 halo zeros never
            // propagate.
            float t1 = (lane < 1) ? g1[i + 1] : g1[i];
            float t2 = (lane < 2) ? g2[i + 1] : g2[i];
            float t3 = (lane < 3) ? g3[i + 1] : g3[i];
            float n1 = __shfl_sync(F, t1, (lane + 1) & 31);
            float n2 = __shfl_sync(F, t2, (lane + 2) & 31);
            float n3 = __shfl_sync(F, t3, (lane + 3) & 31);

            float r = fminf(fminf(g0[i], n1), fminf(n2, n3));

            int s = wbase + 32 * i + lane;
            if (s < OUTW) __stcs(&orow[s], r);
        }
    }
}

extern "C" void kernel_launch(void* const* d_in, const int* in_sizes, int n_in,
                              void* d_out, int out_size)
{
    const float* inp = (const float*)d_in[0];   // (N, 8192) fp32
    const float* w   = (const float*)d_in[1];   // (1, 16)   fp32

    const int N = in_sizes[0] / 8192;           // 1024

    and_conv_kernel<<<N, TPB>>>(
        reinterpret_cast<const float4*>(inp), w, (float*)d_out);
}